// round 1
// baseline (speedup 1.0000x reference)
#include <cuda_runtime.h>
#include <math.h>

// Problem constants
#define S_LEN   2048
#define BATCH   2
#define DMODEL  1024
#define NHEAD   16
#define DHEAD   64
#define MROWS   (S_LEN*BATCH)     // 4096
#define BHEADS  (BATCH*NHEAD)     // 32

// Scratch (device globals; no allocations allowed)
__device__ float g_Q[BHEADS*S_LEN*DHEAD];   // [n][s][dh]
__device__ float g_K[BHEADS*S_LEN*DHEAD];
__device__ float g_V[BHEADS*S_LEN*DHEAD];
__device__ float g_ctx[MROWS*DMODEL];       // (s,b) row-major

// ---------------------------------------------------------------------------
// Fast exp on the FMA pipe (avoids MUFU bottleneck: 134M exps in softmax).
// exp(x) = 2^(x*log2e); magic-number round, degree-5 poly on [-0.5,0.5].
// Max rel err ~2e-6. Valid for x <= 0 (softmax post max-subtraction).
// ---------------------------------------------------------------------------
__device__ __forceinline__ float fast_exp(float x) {
    float y = x * 1.4426950408889634f;
    y = fmaxf(y, -126.0f);
    float t = y + 12582912.0f;                    // 1.5*2^23 magic round
    int   n = __float_as_int(t) - 0x4B400000;     // round(y) as signed int
    float f = y - (t - 12582912.0f);              // frac in [-0.5, 0.5]
    float p = 1.3333558146e-3f;
    p = fmaf(p, f, 9.6181291971e-3f);
    p = fmaf(p, f, 5.5504108664e-2f);
    p = fmaf(p, f, 2.4022650696e-1f);
    p = fmaf(p, f, 6.9314718056e-1f);
    p = fmaf(p, f, 1.0f);
    return __int_as_float(__float_as_int(p) + (n << 23));
}

// ---------------------------------------------------------------------------
// GEMM: out = A(4096x1024) @ W^T (W is 1024x1024 row-major) + bias
// BM=BN=128, BK=16, 256 threads, 8x8 per thread (split 4+4 chunks, float4,
// conflict-free smem reads).
// mode 0/1/2: store to g_Q/g_K/g_V in head layout [(b*H+h)][s][dh]
// mode 3:     A := g_ctx, add resid, store to out (row-major MxN)
// ---------------------------------------------------------------------------
__global__ void __launch_bounds__(256) gemm128(
    const float* __restrict__ A, const float* __restrict__ W,
    const float* __restrict__ bias, const float* __restrict__ resid,
    float* __restrict__ out, int mode)
{
    __shared__ float As[16][132];
    __shared__ float Bs[16][132];

    const int tid = threadIdx.x;
    const int tx  = tid & 15;
    const int ty  = tid >> 4;
    const int row0 = blockIdx.y * 128;
    const int col0 = blockIdx.x * 128;

    const float* Ap = (mode >= 3) ? g_ctx : A;

    float acc[8][8];
    #pragma unroll
    for (int i = 0; i < 8; i++)
        #pragma unroll
        for (int j = 0; j < 8; j++) acc[i][j] = 0.0f;

    const int lr0 = tid >> 2;          // 0..63
    const int lr1 = lr0 + 64;          // 64..127
    const int lk0 = (tid & 3) << 2;    // 0,4,8,12

    for (int k0 = 0; k0 < DMODEL; k0 += 16) {
        float4 a0 = *(const float4*)&Ap[(row0 + lr0) * DMODEL + k0 + lk0];
        float4 a1 = *(const float4*)&Ap[(row0 + lr1) * DMODEL + k0 + lk0];
        float4 b0 = *(const float4*)&W [(col0 + lr0) * DMODEL + k0 + lk0];
        float4 b1 = *(const float4*)&W [(col0 + lr1) * DMODEL + k0 + lk0];

        __syncthreads();
        As[lk0+0][lr0] = a0.x; As[lk0+1][lr0] = a0.y; As[lk0+2][lr0] = a0.z; As[lk0+3][lr0] = a0.w;
        As[lk0+0][lr1] = a1.x; As[lk0+1][lr1] = a1.y; As[lk0+2][lr1] = a1.z; As[lk0+3][lr1] = a1.w;
        Bs[lk0+0][lr0] = b0.x; Bs[lk0+1][lr0] = b0.y; Bs[lk0+2][lr0] = b0.z; Bs[lk0+3][lr0] = b0.w;
        Bs[lk0+0][lr1] = b1.x; Bs[lk0+1][lr1] = b1.y; Bs[lk0+2][lr1] = b1.z; Bs[lk0+3][lr1] = b1.w;
        __syncthreads();

        #pragma unroll
        for (int k = 0; k < 16; k++) {
            float4 x0 = *(const float4*)&As[k][ty * 4];
            float4 x1 = *(const float4*)&As[k][64 + ty * 4];
            float4 y0 = *(const float4*)&Bs[k][tx * 4];
            float4 y1 = *(const float4*)&Bs[k][64 + tx * 4];
            float av[8] = {x0.x, x0.y, x0.z, x0.w, x1.x, x1.y, x1.z, x1.w};
            float bv[8] = {y0.x, y0.y, y0.z, y0.w, y1.x, y1.y, y1.z, y1.w};
            #pragma unroll
            for (int i = 0; i < 8; i++)
                #pragma unroll
                for (int j = 0; j < 8; j++)
                    acc[i][j] = fmaf(av[i], bv[j], acc[i][j]);
        }
    }

    float* qdst = (mode == 0) ? g_Q : (mode == 1) ? g_K : g_V;

    #pragma unroll
    for (int i = 0; i < 8; i++) {
        int r = row0 + ((i < 4) ? (ty * 4 + i) : (64 + ty * 4 + i - 4));
        #pragma unroll
        for (int j = 0; j < 8; j++) {
            int c = col0 + ((j < 4) ? (tx * 4 + j) : (64 + tx * 4 + j - 4));
            float val = acc[i][j] + bias[c];
            if (mode < 3) {
                int s = r >> 1, b = r & 1;        // r = s*B + b, B=2
                int h = c >> 6, dj = c & 63;
                qdst[((b * NHEAD + h) * S_LEN + s) * DHEAD + dj] = val;
            } else {
                out[r * DMODEL + c] = val + resid[r * DMODEL + c];
            }
        }
    }
}

// ---------------------------------------------------------------------------
// Flash attention, fp32, NO 1/sqrt(dh) scaling (matches reference).
// One block = (head n, 64-row q-tile). 256 threads, 4x4 per thread.
// Smem (stride-68 padded, float4-friendly): Qt[d][r], Kt[d][c], Vs[c][jo], Ps[r][c]
// ---------------------------------------------------------------------------
#define SP 68
#define ATTN_SMEM (4 * 64 * SP * 4)

__global__ void __launch_bounds__(256) attn64()
{
    extern __shared__ float sm[];
    float* Qt = sm;                // [64][SP]  transposed: [d][row]
    float* Kt = sm + 64 * SP;      // [64][SP]  transposed: [d][col]
    float* Vs = sm + 2 * 64 * SP;  // [64][SP]  natural:    [col][jo]
    float* Ps = sm + 3 * 64 * SP;  // [64][SP]  natural:    [row][col]

    const int tid = threadIdx.x;
    const int tx  = tid & 15;
    const int ty  = tid >> 4;
    const int n   = blockIdx.y;          // head 0..31 (n = b*16 + h)
    const int q0  = blockIdx.x * 64;

    const float* Qh = g_Q + (size_t)n * S_LEN * DHEAD;
    const float* Kh = g_K + (size_t)n * S_LEN * DHEAD;
    const float* Vh = g_V + (size_t)n * S_LEN * DHEAD;

    // Load Q tile transposed (once per block)
    #pragma unroll
    for (int p = 0; p < 4; p++) {
        int f = tid + p * 256;
        int r = f >> 4, dg = (f & 15) << 2;
        float4 v4 = *(const float4*)&Qh[(q0 + r) * DHEAD + dg];
        Qt[(dg + 0) * SP + r] = v4.x;
        Qt[(dg + 1) * SP + r] = v4.y;
        Qt[(dg + 2) * SP + r] = v4.z;
        Qt[(dg + 3) * SP + r] = v4.w;
    }

    float acc[4][4];
    float m_i[4], l_i[4];
    #pragma unroll
    for (int i = 0; i < 4; i++) {
        m_i[i] = -1e30f; l_i[i] = 0.0f;
        #pragma unroll
        for (int j = 0; j < 4; j++) acc[i][j] = 0.0f;
    }

    for (int t = 0; t < 32; t++) {
        const int k0 = t * 64;
        __syncthreads();  // prev PV done reading Vs/Ps (and Qt visible on t=0)

        #pragma unroll
        for (int p = 0; p < 4; p++) {
            int f = tid + p * 256;
            int r = f >> 4, dg = (f & 15) << 2;
            float4 kv = *(const float4*)&Kh[(k0 + r) * DHEAD + dg];
            Kt[(dg + 0) * SP + r] = kv.x;
            Kt[(dg + 1) * SP + r] = kv.y;
            Kt[(dg + 2) * SP + r] = kv.z;
            Kt[(dg + 3) * SP + r] = kv.w;
            float4 vv = *(const float4*)&Vh[(k0 + r) * DHEAD + dg];
            *(float4*)&Vs[r * SP + dg] = vv;
        }
        __syncthreads();

        // S = Q @ K^T (64x64x64)
        float s4[4][4];
        #pragma unroll
        for (int i = 0; i < 4; i++)
            #pragma unroll
            for (int j = 0; j < 4; j++) s4[i][j] = 0.0f;

        #pragma unroll 8
        for (int d = 0; d < 64; d++) {
            float4 a4 = *(const float4*)&Qt[d * SP + ty * 4];
            float4 b4 = *(const float4*)&Kt[d * SP + tx * 4];
            float av[4] = {a4.x, a4.y, a4.z, a4.w};
            float bv[4] = {b4.x, b4.y, b4.z, b4.w};
            #pragma unroll
            for (int i = 0; i < 4; i++)
                #pragma unroll
                for (int j = 0; j < 4; j++)
                    s4[i][j] = fmaf(av[i], bv[j], s4[i][j]);
        }

        // Online softmax update (row owned by 16 lanes: reduce across tx)
        #pragma unroll
        for (int i = 0; i < 4; i++) {
            float rmax = fmaxf(fmaxf(s4[i][0], s4[i][1]), fmaxf(s4[i][2], s4[i][3]));
            #pragma unroll
            for (int o = 8; o > 0; o >>= 1)
                rmax = fmaxf(rmax, __shfl_xor_sync(0xffffffffu, rmax, o, 16));
            float mnew = fmaxf(m_i[i], rmax);
            float corr = fast_exp(m_i[i] - mnew);
            s4[i][0] = fast_exp(s4[i][0] - mnew);
            s4[i][1] = fast_exp(s4[i][1] - mnew);
            s4[i][2] = fast_exp(s4[i][2] - mnew);
            s4[i][3] = fast_exp(s4[i][3] - mnew);
            float psum = s4[i][0] + s4[i][1] + s4[i][2] + s4[i][3];
            #pragma unroll
            for (int o = 8; o > 0; o >>= 1)
                psum += __shfl_xor_sync(0xffffffffu, psum, o, 16);
            l_i[i] = l_i[i] * corr + psum;
            m_i[i] = mnew;
            acc[i][0] *= corr; acc[i][1] *= corr; acc[i][2] *= corr; acc[i][3] *= corr;
            *(float4*)&Ps[(ty * 4 + i) * SP + tx * 4] =
                make_float4(s4[i][0], s4[i][1], s4[i][2], s4[i][3]);
        }
        __syncthreads();

        // ctx += P @ V (64x64x64)
        #pragma unroll 8
        for (int c = 0; c < 64; c++) {
            float4 b4 = *(const float4*)&Vs[c * SP + tx * 4];
            float bv[4] = {b4.x, b4.y, b4.z, b4.w};
            #pragma unroll
            for (int i = 0; i < 4; i++) {
                float a = Ps[(ty * 4 + i) * SP + c];
                #pragma unroll
                for (int j = 0; j < 4; j++)
                    acc[i][j] = fmaf(a, bv[j], acc[i][j]);
            }
        }
    }

    // Finalize: divide by row sums, write ctx in (s,b,D) layout
    const int b = n >> 4, h = n & 15;
    #pragma unroll
    for (int i = 0; i < 4; i++) {
        float inv = 1.0f / l_i[i];
        int srow = q0 + ty * 4 + i;
        float* dst = g_ctx + ((size_t)srow * BATCH + b) * DMODEL + h * DHEAD + tx * 4;
        dst[0] = acc[i][0] * inv;
        dst[1] = acc[i][1] * inv;
        dst[2] = acc[i][2] * inv;
        dst[3] = acc[i][3] * inv;
    }
}

// ---------------------------------------------------------------------------
// LayerNorm (in-place on out): one block per row of 1024
// ---------------------------------------------------------------------------
__device__ __forceinline__ float block_sum256(float v, float* red)
{
    #pragma unroll
    for (int o = 16; o > 0; o >>= 1) v += __shfl_xor_sync(0xffffffffu, v, o);
    if ((threadIdx.x & 31) == 0) red[threadIdx.x >> 5] = v;
    __syncthreads();
    if (threadIdx.x < 32) {
        float x = (threadIdx.x < 8) ? red[threadIdx.x] : 0.0f;
        #pragma unroll
        for (int o = 4; o > 0; o >>= 1) x += __shfl_xor_sync(0xffffffffu, x, o);
        if (threadIdx.x == 0) red[0] = x;
    }
    __syncthreads();
    float r = red[0];
    __syncthreads();
    return r;
}

__global__ void __launch_bounds__(256) ln_kernel(
    float* __restrict__ y, const float* __restrict__ w, const float* __restrict__ bb)
{
    __shared__ float red[8];
    const int r = blockIdx.x;
    float* row = y + (size_t)r * DMODEL;
    const int tid = threadIdx.x;

    float v[4];
    #pragma unroll
    for (int p = 0; p < 4; p++) v[p] = row[tid + p * 256];

    float s = v[0] + v[1] + v[2] + v[3];
    float mean = block_sum256(s, red) * (1.0f / DMODEL);

    float ss = 0.0f;
    #pragma unroll
    for (int p = 0; p < 4; p++) { float d = v[p] - mean; ss = fmaf(d, d, ss); }
    float var = block_sum256(ss, red) * (1.0f / DMODEL);
    float rstd = rsqrtf(var + 1e-12f);

    #pragma unroll
    for (int p = 0; p < 4; p++) {
        int c = tid + p * 256;
        row[c] = w[c] * (v[p] - mean) * rstd + bb[c];
    }
}

// ---------------------------------------------------------------------------
extern "C" void kernel_launch(void* const* d_in, const int* in_sizes, int n_in,
                              void* d_out, int out_size)
{
    const float* q_in = (const float*)d_in[0];
    const float* k_in = (const float*)d_in[1];
    const float* v_in = (const float*)d_in[2];
    const float* Wq   = (const float*)d_in[3];
    const float* bq   = (const float*)d_in[4];
    const float* Wk   = (const float*)d_in[5];
    const float* bk   = (const float*)d_in[6];
    const float* Wv   = (const float*)d_in[7];
    const float* bv   = (const float*)d_in[8];
    const float* Wo   = (const float*)d_in[9];
    const float* bo   = (const float*)d_in[10];
    const float* ln_w = (const float*)d_in[11];
    const float* ln_b = (const float*)d_in[12];
    float* out = (float*)d_out;

    cudaFuncSetAttribute(attn64, cudaFuncAttributeMaxDynamicSharedMemorySize, ATTN_SMEM);

    dim3 gg(DMODEL / 128, MROWS / 128);   // (8, 32)

    gemm128<<<gg, 256>>>(q_in, Wq, bq, nullptr, nullptr, 0);
    gemm128<<<gg, 256>>>(k_in, Wk, bk, nullptr, nullptr, 1);
    gemm128<<<gg, 256>>>(v_in, Wv, bv, nullptr, nullptr, 2);

    attn64<<<dim3(S_LEN / 64, BHEADS), 256, ATTN_SMEM>>>();

    gemm128<<<gg, 256>>>(nullptr, Wo, bo, q_in, out, 3);

    ln_kernel<<<MROWS, 256>>>(out, ln_w, ln_b);
}

// round 2
// speedup vs baseline: 1.8365x; 1.8365x over previous
#include <cuda_runtime.h>
#include <cuda_bf16.h>
#include <math.h>
#include <stdint.h>

// Problem constants
#define S_LEN   2048
#define BATCH   2
#define DMODEL  1024
#define NHEAD   16
#define DHEAD   64
#define MROWS   (S_LEN*BATCH)     // 4096
#define BHEADS  (BATCH*NHEAD)     // 32

// Scratch (device globals; no allocations allowed)
__device__ float g_Q[BHEADS*S_LEN*DHEAD];   // [n][s][dh]
__device__ float g_K[BHEADS*S_LEN*DHEAD];
__device__ float g_V[BHEADS*S_LEN*DHEAD];
__device__ float g_ctx[MROWS*DMODEL];       // (s,b) row-major

// ---------------------------------------------------------------------------
// Fast exp on the FMA pipe. Valid for x <= 0. Max rel err ~2e-6.
// ---------------------------------------------------------------------------
__device__ __forceinline__ float fast_exp(float x) {
    float y = x * 1.4426950408889634f;
    y = fmaxf(y, -126.0f);
    float t = y + 12582912.0f;
    int   n = __float_as_int(t) - 0x4B400000;
    float f = y - (t - 12582912.0f);
    float p = 1.3333558146e-3f;
    p = fmaf(p, f, 9.6181291971e-3f);
    p = fmaf(p, f, 5.5504108664e-2f);
    p = fmaf(p, f, 2.4022650696e-1f);
    p = fmaf(p, f, 6.9314718056e-1f);
    p = fmaf(p, f, 1.0f);
    return __int_as_float(__float_as_int(p) + (n << 23));
}

// ---------------------------------------------------------------------------
// MMA helpers (bf16 m16n8k16, fp32 accumulate)
// ---------------------------------------------------------------------------
__device__ __forceinline__ uint32_t b2u(__nv_bfloat162 v) {
    uint32_t u; memcpy(&u, &v, 4); return u;
}

// Split two floats into packed bf16 hi pair (returned) and lo pair (out param).
__device__ __forceinline__ uint32_t split2(float x, float y, uint32_t& lo) {
    __nv_bfloat16 hx = __float2bfloat16_rn(x);
    __nv_bfloat16 hy = __float2bfloat16_rn(y);
    __nv_bfloat162 h; h.x = hx; h.y = hy;
    __nv_bfloat162 l = __floats2bfloat162_rn(x - __bfloat162float(hx),
                                             y - __bfloat162float(hy));
    lo = b2u(l);
    return b2u(h);
}

// Convert float4 -> 4 hi bf16 + 4 lo bf16, stored contiguously.
__device__ __forceinline__ void cvt_store(__nv_bfloat16* hb, __nv_bfloat16* lb, float4 v) {
    uint32_t l0, l1;
    uint32_t h0 = split2(v.x, v.y, l0);
    uint32_t h1 = split2(v.z, v.w, l1);
    ((uint32_t*)hb)[0] = h0; ((uint32_t*)hb)[1] = h1;
    ((uint32_t*)lb)[0] = l0; ((uint32_t*)lb)[1] = l1;
}

__device__ __forceinline__ void ldsm4(uint32_t* r, const __nv_bfloat16* p) {
    uint32_t a = (uint32_t)__cvta_generic_to_shared(p);
    asm volatile("ldmatrix.sync.aligned.m8n8.x4.shared.b16 {%0,%1,%2,%3}, [%4];"
        : "=r"(r[0]), "=r"(r[1]), "=r"(r[2]), "=r"(r[3]) : "r"(a));
}

__device__ __forceinline__ void mma16816(float* d, const uint32_t* a,
                                         uint32_t b0, uint32_t b1) {
    asm volatile(
        "mma.sync.aligned.m16n8k16.row.col.f32.bf16.bf16.f32 "
        "{%0,%1,%2,%3},{%4,%5,%6,%7},{%8,%9},{%0,%1,%2,%3};"
        : "+f"(d[0]), "+f"(d[1]), "+f"(d[2]), "+f"(d[3])
        : "r"(a[0]), "r"(a[1]), "r"(a[2]), "r"(a[3]), "r"(b0), "r"(b1));
}

// ---------------------------------------------------------------------------
// GEMM: out = A(4096x1024) @ W^T + bias, bf16x3 tensor-core path.
// Block 128x128, BK=32, 8 warps (2x4), warp tile 64x32.
// mode 0/1/2: store to g_Q/g_K/g_V head layout; mode 3: A=g_ctx, +resid -> out
// ---------------------------------------------------------------------------
#define GST 40   // smem tile stride in bf16 elems (80B rows: conflict-free ldsm)

__global__ void __launch_bounds__(256) gemm_mma(
    const float* __restrict__ A, const float* __restrict__ W,
    const float* __restrict__ bias, const float* __restrict__ resid,
    float* __restrict__ out, int mode)
{
    __shared__ __nv_bfloat16 sAh[128*GST], sAl[128*GST];
    __shared__ __nv_bfloat16 sBh[128*GST], sBl[128*GST];

    const int tid  = threadIdx.x;
    const int lane = tid & 31;
    const int wid  = tid >> 5;
    const int wm   = (wid >> 2) * 64;
    const int wn   = (wid & 3) * 32;
    const int row0 = blockIdx.y * 128;
    const int col0 = blockIdx.x * 128;
    const float* Ap = (mode >= 3) ? g_ctx : A;

    float acc[4][4][4] = {};

    const int lr = tid >> 3;          // 0..31
    const int lc = (tid & 7) * 4;     // 0..28

    // ldmatrix source offsets (per-lane)
    const int lrow = lane & 15;
    const int lcol = (lane >> 4) * 8;

    // prefetch tile 0
    float4 av[4], bv[4];
    #pragma unroll
    for (int p = 0; p < 4; p++) {
        av[p] = *(const float4*)&Ap[(size_t)(row0 + lr + p*32) * DMODEL + lc];
        bv[p] = *(const float4*)&W [(size_t)(col0 + lr + p*32) * DMODEL + lc];
    }

    for (int k0 = 0; k0 < DMODEL; k0 += 32) {
        __syncthreads();
        #pragma unroll
        for (int p = 0; p < 4; p++) {
            int r = lr + p*32;
            cvt_store(&sAh[r*GST + lc], &sAl[r*GST + lc], av[p]);
            cvt_store(&sBh[r*GST + lc], &sBl[r*GST + lc], bv[p]);
        }
        __syncthreads();

        if (k0 + 32 < DMODEL) {
            #pragma unroll
            for (int p = 0; p < 4; p++) {
                av[p] = *(const float4*)&Ap[(size_t)(row0 + lr + p*32) * DMODEL + k0 + 32 + lc];
                bv[p] = *(const float4*)&W [(size_t)(col0 + lr + p*32) * DMODEL + k0 + 32 + lc];
            }
        }

        #pragma unroll
        for (int ks = 0; ks < 2; ks++) {
            uint32_t ah[4][4], al[4][4], bh[2][4], bl[2][4];
            #pragma unroll
            for (int im = 0; im < 4; im++) {
                int off = (wm + im*16 + lrow) * GST + ks*16 + lcol;
                ldsm4(ah[im], &sAh[off]);
                ldsm4(al[im], &sAl[off]);
            }
            #pragma unroll
            for (int g = 0; g < 2; g++) {
                int off = (wn + g*16 + lrow) * GST + ks*16 + lcol;
                ldsm4(bh[g], &sBh[off]);
                ldsm4(bl[g], &sBl[off]);
            }
            #pragma unroll
            for (int im = 0; im < 4; im++)
                #pragma unroll
                for (int jn = 0; jn < 4; jn++) {
                    int g = jn >> 1, o = jn & 1;
                    mma16816(acc[im][jn], ah[im], bh[g][o], bh[g][o+2]);
                    mma16816(acc[im][jn], ah[im], bl[g][o], bl[g][o+2]);
                    mma16816(acc[im][jn], al[im], bh[g][o], bh[g][o+2]);
                }
        }
    }

    float* qdst = (mode == 0) ? g_Q : (mode == 1) ? g_K : g_V;

    #pragma unroll
    for (int im = 0; im < 4; im++) {
        #pragma unroll
        for (int jn = 0; jn < 4; jn++) {
            int rg = row0 + wm + im*16 + (lane >> 2);
            int cg = col0 + wn + jn*8 + (lane & 3)*2;
            float v0 = acc[im][jn][0] + bias[cg];
            float v1 = acc[im][jn][1] + bias[cg+1];
            float v2 = acc[im][jn][2] + bias[cg];
            float v3 = acc[im][jn][3] + bias[cg+1];
            if (mode < 3) {
                int s0 = rg >> 1, b0b = rg & 1;
                int s1 = (rg+8) >> 1, b1b = (rg+8) & 1;
                int h = cg >> 6, dj = cg & 63;
                *(float2*)&qdst[(((size_t)b0b*NHEAD + h)*S_LEN + s0)*DHEAD + dj] = make_float2(v0, v1);
                *(float2*)&qdst[(((size_t)b1b*NHEAD + h)*S_LEN + s1)*DHEAD + dj] = make_float2(v2, v3);
            } else {
                const float* rr0 = &resid[(size_t)rg * DMODEL + cg];
                const float* rr1 = &resid[(size_t)(rg+8) * DMODEL + cg];
                *(float2*)&out[(size_t)rg * DMODEL + cg]     = make_float2(v0 + rr0[0], v1 + rr0[1]);
                *(float2*)&out[(size_t)(rg+8) * DMODEL + cg] = make_float2(v2 + rr1[0], v3 + rr1[1]);
            }
        }
    }
}

// ---------------------------------------------------------------------------
// Flash attention, bf16x3 tensor cores, NO 1/sqrt(dh) scaling.
// Block = (head, 128 q-rows), 8 warps, warp owns 16 q-rows x full 64 kv/dh.
// P stays in registers (QK acc layout == PV A-frag layout).
// ---------------------------------------------------------------------------
#define AST 72   // smem stride (144B rows: conflict-free ldsm)
#define ATTN_SMEM ((2*128*AST + 4*64*AST) * 2)

__global__ void __launch_bounds__(256) attn_mma()
{
    extern __shared__ __nv_bfloat16 sm[];
    __nv_bfloat16* Qh = sm;
    __nv_bfloat16* Ql = Qh + 128*AST;
    __nv_bfloat16* Kh = Ql + 128*AST;
    __nv_bfloat16* Kl = Kh + 64*AST;
    __nv_bfloat16* Vh = Kl + 64*AST;
    __nv_bfloat16* Vl = Vh + 64*AST;

    const int tid  = threadIdx.x;
    const int lane = tid & 31;
    const int wid  = tid >> 5;
    const int wm   = wid * 16;
    const int n    = blockIdx.y;           // head index (b*16 + h)
    const int q0   = blockIdx.x * 128;

    const float* Qg = g_Q + (size_t)n * S_LEN * DHEAD;
    const float* Kg = g_K + (size_t)n * S_LEN * DHEAD;
    const float* Vg = g_V + (size_t)n * S_LEN * DHEAD;

    const int r  = tid >> 4;          // 0..15
    const int c4 = (tid & 15) * 4;    // 0..60
    const int lrow = lane & 15;
    const int lcol = (lane >> 4) * 8;

    // Load Q tile (128x64) -> hi/lo smem
    #pragma unroll
    for (int p = 0; p < 8; p++) {
        int rr = r + p*16;
        float4 v = *(const float4*)&Qg[(size_t)(q0 + rr) * DHEAD + c4];
        cvt_store(&Qh[rr*AST + c4], &Ql[rr*AST + c4], v);
    }

    float ctx[8][4] = {};
    float m0 = -1e30f, m1 = -1e30f, l0 = 0.0f, l1 = 0.0f;

    // Prefetch KV tile 0
    float4 kreg[4], vreg[4];
    #pragma unroll
    for (int p = 0; p < 4; p++) {
        kreg[p] = *(const float4*)&Kg[(size_t)(r + p*16) * DHEAD + c4];
        vreg[p] = *(const float4*)&Vg[(size_t)(r + p*16) * DHEAD + c4];
    }

    for (int t = 0; t < 32; t++) {
        __syncthreads();
        // Store K tile [kv][d], V tile transposed [d][kv]
        #pragma unroll
        for (int p = 0; p < 4; p++) {
            int rr = r + p*16;
            cvt_store(&Kh[rr*AST + c4], &Kl[rr*AST + c4], kreg[p]);
            float vv[4] = {vreg[p].x, vreg[p].y, vreg[p].z, vreg[p].w};
            #pragma unroll
            for (int j = 0; j < 4; j++) {
                __nv_bfloat16 hb = __float2bfloat16_rn(vv[j]);
                Vh[(c4+j)*AST + rr] = hb;
                Vl[(c4+j)*AST + rr] = __float2bfloat16_rn(vv[j] - __bfloat162float(hb));
            }
        }
        __syncthreads();

        if (t + 1 < 32) {
            const float* Kg2 = Kg + (size_t)(t+1) * 64 * DHEAD;
            const float* Vg2 = Vg + (size_t)(t+1) * 64 * DHEAD;
            #pragma unroll
            for (int p = 0; p < 4; p++) {
                kreg[p] = *(const float4*)&Kg2[(size_t)(r + p*16) * DHEAD + c4];
                vreg[p] = *(const float4*)&Vg2[(size_t)(r + p*16) * DHEAD + c4];
            }
        }

        // S = Q @ K^T  (16 rows x 64 kv per warp)
        float sa[8][4] = {};
        #pragma unroll
        for (int kk = 0; kk < 4; kk++) {
            uint32_t qh4[4], ql4[4];
            int qoff = (wm + lrow) * AST + kk*16 + lcol;
            ldsm4(qh4, &Qh[qoff]);
            ldsm4(ql4, &Ql[qoff]);
            uint32_t khf[4][4], klf[4][4];
            #pragma unroll
            for (int g = 0; g < 4; g++) {
                int off = (g*16 + lrow) * AST + kk*16 + lcol;
                ldsm4(khf[g], &Kh[off]);
                ldsm4(klf[g], &Kl[off]);
            }
            #pragma unroll
            for (int jn = 0; jn < 8; jn++) {
                int g = jn >> 1, o = jn & 1;
                mma16816(sa[jn], qh4, khf[g][o], khf[g][o+2]);
                mma16816(sa[jn], qh4, klf[g][o], klf[g][o+2]);
                mma16816(sa[jn], ql4, khf[g][o], khf[g][o+2]);
            }
        }

        // Online softmax: lane owns rows (l>>2) via d0,d1 and (l>>2)+8 via d2,d3
        float mx0 = -1e30f, mx1 = -1e30f;
        #pragma unroll
        for (int jn = 0; jn < 8; jn++) {
            mx0 = fmaxf(mx0, fmaxf(sa[jn][0], sa[jn][1]));
            mx1 = fmaxf(mx1, fmaxf(sa[jn][2], sa[jn][3]));
        }
        mx0 = fmaxf(mx0, __shfl_xor_sync(0xffffffffu, mx0, 1));
        mx0 = fmaxf(mx0, __shfl_xor_sync(0xffffffffu, mx0, 2));
        mx1 = fmaxf(mx1, __shfl_xor_sync(0xffffffffu, mx1, 1));
        mx1 = fmaxf(mx1, __shfl_xor_sync(0xffffffffu, mx1, 2));

        float mn0 = fmaxf(m0, mx0), mn1 = fmaxf(m1, mx1);
        float c0 = fast_exp(m0 - mn0), c1 = fast_exp(m1 - mn1);
        float s0 = 0.0f, s1 = 0.0f;
        #pragma unroll
        for (int jn = 0; jn < 8; jn++) {
            sa[jn][0] = fast_exp(sa[jn][0] - mn0);
            sa[jn][1] = fast_exp(sa[jn][1] - mn0);
            sa[jn][2] = fast_exp(sa[jn][2] - mn1);
            sa[jn][3] = fast_exp(sa[jn][3] - mn1);
            s0 += sa[jn][0] + sa[jn][1];
            s1 += sa[jn][2] + sa[jn][3];
            ctx[jn][0] *= c0; ctx[jn][1] *= c0;
            ctx[jn][2] *= c1; ctx[jn][3] *= c1;
        }
        s0 += __shfl_xor_sync(0xffffffffu, s0, 1);
        s0 += __shfl_xor_sync(0xffffffffu, s0, 2);
        s1 += __shfl_xor_sync(0xffffffffu, s1, 1);
        s1 += __shfl_xor_sync(0xffffffffu, s1, 2);
        l0 = l0 * c0 + s0;  m0 = mn0;
        l1 = l1 * c1 + s1;  m1 = mn1;

        // Pack P fragments directly from registers (QK acc layout == PV A layout)
        uint32_t ph[4][4], pl[4][4];
        #pragma unroll
        for (int kc = 0; kc < 4; kc++) {
            ph[kc][0] = split2(sa[2*kc][0],   sa[2*kc][1],   pl[kc][0]);
            ph[kc][1] = split2(sa[2*kc][2],   sa[2*kc][3],   pl[kc][1]);
            ph[kc][2] = split2(sa[2*kc+1][0], sa[2*kc+1][1], pl[kc][2]);
            ph[kc][3] = split2(sa[2*kc+1][2], sa[2*kc+1][3], pl[kc][3]);
        }

        // ctx += P @ V
        #pragma unroll
        for (int kc = 0; kc < 4; kc++) {
            uint32_t vhf[4][4], vlf[4][4];
            #pragma unroll
            for (int g = 0; g < 4; g++) {
                int off = (g*16 + lrow) * AST + kc*16 + lcol;
                ldsm4(vhf[g], &Vh[off]);
                ldsm4(vlf[g], &Vl[off]);
            }
            #pragma unroll
            for (int jn = 0; jn < 8; jn++) {
                int g = jn >> 1, o = jn & 1;
                mma16816(ctx[jn], ph[kc], vhf[g][o], vhf[g][o+2]);
                mma16816(ctx[jn], ph[kc], vlf[g][o], vlf[g][o+2]);
                mma16816(ctx[jn], pl[kc], vhf[g][o], vhf[g][o+2]);
            }
        }
    }

    // Finalize: divide by row sums, write g_ctx in (s,b,D) layout
    const int b = n >> 4, h = n & 15;
    const float inv0 = 1.0f / l0, inv1 = 1.0f / l1;
    const int s0r = q0 + wm + (lane >> 2);
    #pragma unroll
    for (int jn = 0; jn < 8; jn++) {
        int dh = jn*8 + (lane & 3)*2;
        *(float2*)&g_ctx[((size_t)s0r * BATCH + b) * DMODEL + h*DHEAD + dh] =
            make_float2(ctx[jn][0]*inv0, ctx[jn][1]*inv0);
        *(float2*)&g_ctx[((size_t)(s0r+8) * BATCH + b) * DMODEL + h*DHEAD + dh] =
            make_float2(ctx[jn][2]*inv1, ctx[jn][3]*inv1);
    }
}

// ---------------------------------------------------------------------------
// LayerNorm (in-place): one block per row of 1024
// ---------------------------------------------------------------------------
__device__ __forceinline__ float block_sum256(float v, float* red)
{
    #pragma unroll
    for (int o = 16; o > 0; o >>= 1) v += __shfl_xor_sync(0xffffffffu, v, o);
    if ((threadIdx.x & 31) == 0) red[threadIdx.x >> 5] = v;
    __syncthreads();
    if (threadIdx.x < 32) {
        float x = (threadIdx.x < 8) ? red[threadIdx.x] : 0.0f;
        #pragma unroll
        for (int o = 4; o > 0; o >>= 1) x += __shfl_xor_sync(0xffffffffu, x, o);
        if (threadIdx.x == 0) red[0] = x;
    }
    __syncthreads();
    float rv = red[0];
    __syncthreads();
    return rv;
}

__global__ void __launch_bounds__(256) ln_kernel(
    float* __restrict__ y, const float* __restrict__ w, const float* __restrict__ bb)
{
    __shared__ float red[8];
    const int rix = blockIdx.x;
    float* row = y + (size_t)rix * DMODEL;
    const int tid = threadIdx.x;

    float v[4];
    #pragma unroll
    for (int p = 0; p < 4; p++) v[p] = row[tid + p * 256];

    float s = v[0] + v[1] + v[2] + v[3];
    float mean = block_sum256(s, red) * (1.0f / DMODEL);

    float ss = 0.0f;
    #pragma unroll
    for (int p = 0; p < 4; p++) { float d = v[p] - mean; ss = fmaf(d, d, ss); }
    float var = block_sum256(ss, red) * (1.0f / DMODEL);
    float rstd = rsqrtf(var + 1e-12f);

    #pragma unroll
    for (int p = 0; p < 4; p++) {
        int c = tid + p * 256;
        row[c] = w[c] * (v[p] - mean) * rstd + bb[c];
    }
}

// ---------------------------------------------------------------------------
extern "C" void kernel_launch(void* const* d_in, const int* in_sizes, int n_in,
                              void* d_out, int out_size)
{
    const float* q_in = (const float*)d_in[0];
    const float* k_in = (const float*)d_in[1];
    const float* v_in = (const float*)d_in[2];
    const float* Wq   = (const float*)d_in[3];
    const float* bq   = (const float*)d_in[4];
    const float* Wk   = (const float*)d_in[5];
    const float* bk   = (const float*)d_in[6];
    const float* Wv   = (const float*)d_in[7];
    const float* bv   = (const float*)d_in[8];
    const float* Wo   = (const float*)d_in[9];
    const float* bo   = (const float*)d_in[10];
    const float* ln_w = (const float*)d_in[11];
    const float* ln_b = (const float*)d_in[12];
    float* out = (float*)d_out;

    cudaFuncSetAttribute(attn_mma, cudaFuncAttributeMaxDynamicSharedMemorySize, ATTN_SMEM);

    dim3 gg(DMODEL / 128, MROWS / 128);   // (8, 32)

    gemm_mma<<<gg, 256>>>(q_in, Wq, bq, nullptr, nullptr, 0);
    gemm_mma<<<gg, 256>>>(k_in, Wk, bk, nullptr, nullptr, 1);
    gemm_mma<<<gg, 256>>>(v_in, Wv, bv, nullptr, nullptr, 2);

    attn_mma<<<dim3(S_LEN / 128, BHEADS), 256, ATTN_SMEM>>>();

    gemm_mma<<<gg, 256>>>(nullptr, Wo, bo, q_in, out, 3);

    ln_kernel<<<MROWS, 256>>>(out, ln_w, ln_b);
}

// round 3
// speedup vs baseline: 2.1418x; 1.1663x over previous
#include <cuda_runtime.h>
#include <cuda_bf16.h>
#include <stdint.h>

#define S_LEN   2048
#define BATCH   2
#define DMODEL  1024
#define NHEAD   16
#define DHEAD   64
#define MROWS   4096
#define BHEADS  32
#define NELEM   (MROWS*DMODEL)    // 4,194,304
#define WELEM   (DMODEL*DMODEL)   // 1,048,576

// Pre-split bf16 hi/lo buffers (device globals; no allocations allowed)
__device__ __nv_bfloat16 g_Ah[3][NELEM], g_Al[3][NELEM];   // activations q,k,v
__device__ __nv_bfloat16 g_Wh[4][WELEM], g_Wl[4][WELEM];   // weights q,k,v,o
__device__ __nv_bfloat16 g_Qh[NELEM], g_Ql[NELEM];         // head layout [n][s][64]
__device__ __nv_bfloat16 g_Kh[NELEM], g_Kl[NELEM];
__device__ __nv_bfloat16 g_Vh[NELEM], g_Vl[NELEM];
__device__ __nv_bfloat16 g_Ch[NELEM], g_Cl[NELEM];         // ctx (s,b,D) row-major

// ---------------------------------------------------------------------------
__device__ __forceinline__ float fast_exp(float x) {
    float y = x * 1.4426950408889634f;
    y = fmaxf(y, -126.0f);
    float t = y + 12582912.0f;
    int   n = __float_as_int(t) - 0x4B400000;
    float f = y - (t - 12582912.0f);
    float p = 1.3333558146e-3f;
    p = fmaf(p, f, 9.6181291971e-3f);
    p = fmaf(p, f, 5.5504108664e-2f);
    p = fmaf(p, f, 2.4022650696e-1f);
    p = fmaf(p, f, 6.9314718056e-1f);
    p = fmaf(p, f, 1.0f);
    return __int_as_float(__float_as_int(p) + (n << 23));
}

__device__ __forceinline__ uint32_t b2u(__nv_bfloat162 v) {
    uint32_t u; memcpy(&u, &v, 4); return u;
}
__device__ __forceinline__ uint32_t split2(float x, float y, uint32_t& lo) {
    __nv_bfloat16 hx = __float2bfloat16_rn(x);
    __nv_bfloat16 hy = __float2bfloat16_rn(y);
    __nv_bfloat162 h; h.x = hx; h.y = hy;
    __nv_bfloat162 l = __floats2bfloat162_rn(x - __bfloat162float(hx),
                                             y - __bfloat162float(hy));
    lo = b2u(l);
    return b2u(h);
}

__device__ __forceinline__ void ldsm4(uint32_t* r, const __nv_bfloat16* p) {
    uint32_t a = (uint32_t)__cvta_generic_to_shared(p);
    asm volatile("ldmatrix.sync.aligned.m8n8.x4.shared.b16 {%0,%1,%2,%3}, [%4];"
        : "=r"(r[0]), "=r"(r[1]), "=r"(r[2]), "=r"(r[3]) : "r"(a));
}
__device__ __forceinline__ void ldsm4t(uint32_t* r, const __nv_bfloat16* p) {
    uint32_t a = (uint32_t)__cvta_generic_to_shared(p);
    asm volatile("ldmatrix.sync.aligned.m8n8.x4.trans.shared.b16 {%0,%1,%2,%3}, [%4];"
        : "=r"(r[0]), "=r"(r[1]), "=r"(r[2]), "=r"(r[3]) : "r"(a));
}
__device__ __forceinline__ void mma16816(float* d, const uint32_t* a,
                                         uint32_t b0, uint32_t b1) {
    asm volatile(
        "mma.sync.aligned.m16n8k16.row.col.f32.bf16.bf16.f32 "
        "{%0,%1,%2,%3},{%4,%5,%6,%7},{%8,%9},{%0,%1,%2,%3};"
        : "+f"(d[0]), "+f"(d[1]), "+f"(d[2]), "+f"(d[3])
        : "r"(a[0]), "r"(a[1]), "r"(a[2]), "r"(a[3]), "r"(b0), "r"(b1));
}
__device__ __forceinline__ void cpa16(uint32_t dst, const void* src) {
    asm volatile("cp.async.cg.shared.global [%0], [%1], 16;\n" :: "r"(dst), "l"(src));
}
__device__ __forceinline__ void cp_commit() {
    asm volatile("cp.async.commit_group;\n");
}
template<int N> __device__ __forceinline__ void cp_wait() {
    asm volatile("cp.async.wait_group %0;\n" :: "n"(N));
}

// ---------------------------------------------------------------------------
// Split all inputs fp32 -> bf16 hi/lo. grid (1024, 16): y<12 acts, y>=12 weights.
// ---------------------------------------------------------------------------
__global__ void __launch_bounds__(256) split_all(
    const float* __restrict__ q, const float* __restrict__ k, const float* __restrict__ v,
    const float* __restrict__ wq, const float* __restrict__ wk,
    const float* __restrict__ wv, const float* __restrict__ wo)
{
    int yy = blockIdx.y;
    const float* src; __nv_bfloat16 *dh, *dl;
    size_t off;
    if (yy < 12) {
        int t = yy >> 2; off = (size_t)(yy & 3) * WELEM;
        src = (t == 0) ? q : (t == 1) ? k : v;
        dh = g_Ah[t]; dl = g_Al[t];
    } else {
        int t = yy - 12; off = 0;
        src = (t == 0) ? wq : (t == 1) ? wk : (t == 2) ? wv : wo;
        dh = g_Wh[t]; dl = g_Wl[t];
    }
    size_t i = off + ((size_t)blockIdx.x * 256 + threadIdx.x) * 4;
    float4 vv = *(const float4*)&src[i];
    uint32_t l0, l1;
    uint32_t h0 = split2(vv.x, vv.y, l0);
    uint32_t h1 = split2(vv.z, vv.w, l1);
    *(uint2*)&dh[i] = make_uint2(h0, h1);
    *(uint2*)&dl[i] = make_uint2(l0, l1);
}

// ---------------------------------------------------------------------------
// GEMM: out = A(4096x1024) @ W^T + bias, bf16x3, cp.async double-buffered.
// Block 128x128, BK=32, 8 warps (2x4), warp tile 64x32.
// ---------------------------------------------------------------------------
#define GST 40                       // smem row stride (80B): conflict-free ldsm
#define GARR (128*GST)               // elems per array per stage
#define GEMM_SMEM (2*4*GARR*2)       // 81,920 bytes

__global__ void __launch_bounds__(256,2) gemm_mma(
    const float* __restrict__ bias, const float* __restrict__ resid,
    float* __restrict__ out, int mode)
{
    extern __shared__ __nv_bfloat16 sg[];

    const int tid  = threadIdx.x;
    const int lane = tid & 31;
    const int wid  = tid >> 5;
    const int wm   = (wid >> 2) * 64;
    const int wn   = (wid & 3) * 32;
    const int row0 = blockIdx.y * 128;
    const int col0 = blockIdx.x * 128;
    const int lrow = lane & 15;
    const int lcol = (lane >> 4) * 8;

    const __nv_bfloat16 *Ah, *Al, *Bh, *Bl;
    __nv_bfloat16 *Oh = nullptr, *Ol = nullptr;
    switch (mode) {
        case 0: Ah = g_Ah[0]; Al = g_Al[0]; Bh = g_Wh[0]; Bl = g_Wl[0]; Oh = g_Qh; Ol = g_Ql; break;
        case 1: Ah = g_Ah[1]; Al = g_Al[1]; Bh = g_Wh[1]; Bl = g_Wl[1]; Oh = g_Kh; Ol = g_Kl; break;
        case 2: Ah = g_Ah[2]; Al = g_Al[2]; Bh = g_Wh[2]; Bl = g_Wl[2]; Oh = g_Vh; Ol = g_Vl; break;
        default: Ah = g_Ch;   Al = g_Cl;   Bh = g_Wh[3]; Bl = g_Wl[3]; break;
    }
    const __nv_bfloat16* srcs[4] = {Ah, Al, Bh, Bl};

    const uint32_t smb = (uint32_t)__cvta_generic_to_shared(sg);
    const int rw = tid >> 1;              // 0..127
    const int cofs = (tid & 1) * 16;      // 0 or 16 (bf16 elems)

    float acc[4][4][4] = {};

    // issue stage 0
    {
        #pragma unroll
        for (int a = 0; a < 4; a++) {
            const __nv_bfloat16* p = srcs[a] +
                (size_t)((a < 2 ? row0 : col0) + rw) * DMODEL + cofs;
            uint32_t d = smb + (uint32_t)((a * GARR + rw * GST + cofs) * 2);
            cpa16(d, p); cpa16(d + 16, p + 8);
        }
        cp_commit();
    }

    for (int it = 0; it < 32; it++) {
        if (it + 1 < 32) {
            int k0 = (it + 1) * 32, s = (it + 1) & 1;
            #pragma unroll
            for (int a = 0; a < 4; a++) {
                const __nv_bfloat16* p = srcs[a] +
                    (size_t)((a < 2 ? row0 : col0) + rw) * DMODEL + k0 + cofs;
                uint32_t d = smb + (uint32_t)(((s * 4 + a) * GARR + rw * GST + cofs) * 2);
                cpa16(d, p); cpa16(d + 16, p + 8);
            }
            cp_commit();
            cp_wait<1>();
        } else {
            cp_wait<0>();
        }
        __syncthreads();

        const int bf = it & 1;
        const __nv_bfloat16* sAh = sg + (bf * 4 + 0) * GARR;
        const __nv_bfloat16* sAl = sg + (bf * 4 + 1) * GARR;
        const __nv_bfloat16* sBh = sg + (bf * 4 + 2) * GARR;
        const __nv_bfloat16* sBl = sg + (bf * 4 + 3) * GARR;

        #pragma unroll
        for (int ks = 0; ks < 2; ks++) {
            uint32_t bhf[2][4], blf[2][4];
            #pragma unroll
            for (int gg = 0; gg < 2; gg++) {
                int off = (wn + gg * 16 + lrow) * GST + ks * 16 + lcol;
                ldsm4(bhf[gg], &sBh[off]);
                ldsm4(blf[gg], &sBl[off]);
            }
            #pragma unroll
            for (int im = 0; im < 4; im++) {
                uint32_t ahf[4], alf[4];
                int off = (wm + im * 16 + lrow) * GST + ks * 16 + lcol;
                ldsm4(ahf, &sAh[off]);
                ldsm4(alf, &sAl[off]);
                #pragma unroll
                for (int jn = 0; jn < 4; jn++) {
                    int g = jn >> 1, o = jn & 1;
                    mma16816(acc[im][jn], ahf, bhf[g][o], bhf[g][o+2]);
                    mma16816(acc[im][jn], ahf, blf[g][o], blf[g][o+2]);
                    mma16816(acc[im][jn], alf, bhf[g][o], bhf[g][o+2]);
                }
            }
        }
        __syncthreads();
    }

    #pragma unroll
    for (int im = 0; im < 4; im++) {
        #pragma unroll
        for (int jn = 0; jn < 4; jn++) {
            int rg = row0 + wm + im * 16 + (lane >> 2);
            int cg = col0 + wn + jn * 8 + (lane & 3) * 2;
            float v0 = acc[im][jn][0] + bias[cg];
            float v1 = acc[im][jn][1] + bias[cg+1];
            float v2 = acc[im][jn][2] + bias[cg];
            float v3 = acc[im][jn][3] + bias[cg+1];
            if (mode < 3) {
                // head layout [n][s][64], split hi/lo
                int s0 = rg >> 1, b0b = rg & 1;
                int s1 = (rg + 8) >> 1, b1b = (rg + 8) & 1;
                int h = cg >> 6, dj = cg & 63;
                size_t o0 = (((size_t)b0b * NHEAD + h) * S_LEN + s0) * DHEAD + dj;
                size_t o1 = (((size_t)b1b * NHEAD + h) * S_LEN + s1) * DHEAD + dj;
                uint32_t lo;
                uint32_t hi = split2(v0, v1, lo);
                *(uint32_t*)&Oh[o0] = hi; *(uint32_t*)&Ol[o0] = lo;
                hi = split2(v2, v3, lo);
                *(uint32_t*)&Oh[o1] = hi; *(uint32_t*)&Ol[o1] = lo;
            } else {
                const float* rr0 = &resid[(size_t)rg * DMODEL + cg];
                const float* rr1 = &resid[(size_t)(rg+8) * DMODEL + cg];
                *(float2*)&out[(size_t)rg * DMODEL + cg]     = make_float2(v0 + rr0[0], v1 + rr0[1]);
                *(float2*)&out[(size_t)(rg+8) * DMODEL + cg] = make_float2(v2 + rr1[0], v3 + rr1[1]);
            }
        }
    }
}

// ---------------------------------------------------------------------------
// Flash attention, bf16x3, cp.async double-buffered KV, Q-frags in registers.
// Block = (head, 128 q-rows), 8 warps, warp owns 16 q-rows x 64 kv.
// V consumed in natural [kv][dh] layout via ldmatrix.trans.
// ---------------------------------------------------------------------------
#define AST 72                        // smem row stride (144B): conflict-free
#define AARR (64*AST)                 // elems per array per stage
#define ATTN_SMEM (2*4*AARR*2)        // 73,728 bytes

__global__ void __launch_bounds__(256,2) attn_mma()
{
    extern __shared__ __nv_bfloat16 sa_mem[];

    const int tid  = threadIdx.x;
    const int lane = tid & 31;
    const int wid  = tid >> 5;
    const int wm   = wid * 16;
    const int n    = blockIdx.y;
    const int q0   = blockIdx.x * 128;
    const int lrow = lane & 15;
    const int lcol = (lane >> 4) * 8;

    const size_t hofs = (size_t)n * S_LEN * DHEAD;
    const __nv_bfloat16* Qh_g = g_Qh + hofs;
    const __nv_bfloat16* Ql_g = g_Ql + hofs;
    const __nv_bfloat16* srcs[4] = {g_Kh + hofs, g_Kl + hofs, g_Vh + hofs, g_Vl + hofs};

    const uint32_t smb = (uint32_t)__cvta_generic_to_shared(sa_mem);
    const int rw = tid >> 2;              // 0..63
    const int cofs = (tid & 3) * 16;      // 0,16,32,48

    // Q fragments in registers (reused across all KV tiles)
    uint32_t qh[4][4], ql[4][4];
    {
        const int qr = q0 + wm + (lane >> 2);
        const int qc = (lane & 3) * 2;
        #pragma unroll
        for (int kk = 0; kk < 4; kk++) {
            size_t b0 = (size_t)qr * DHEAD + kk * 16 + qc;
            qh[kk][0] = *(const uint32_t*)&Qh_g[b0];
            qh[kk][1] = *(const uint32_t*)&Qh_g[b0 + 8*DHEAD];
            qh[kk][2] = *(const uint32_t*)&Qh_g[b0 + 8];
            qh[kk][3] = *(const uint32_t*)&Qh_g[b0 + 8*DHEAD + 8];
            ql[kk][0] = *(const uint32_t*)&Ql_g[b0];
            ql[kk][1] = *(const uint32_t*)&Ql_g[b0 + 8*DHEAD];
            ql[kk][2] = *(const uint32_t*)&Ql_g[b0 + 8];
            ql[kk][3] = *(const uint32_t*)&Ql_g[b0 + 8*DHEAD + 8];
        }
    }

    float ctx[8][4] = {};
    float m0 = -1e30f, m1 = -1e30f, l0 = 0.0f, l1 = 0.0f;

    // issue stage 0
    {
        #pragma unroll
        for (int a = 0; a < 4; a++) {
            const __nv_bfloat16* p = srcs[a] + (size_t)rw * DHEAD + cofs;
            uint32_t d = smb + (uint32_t)((a * AARR + rw * AST + cofs) * 2);
            cpa16(d, p); cpa16(d + 16, p + 8);
        }
        cp_commit();
    }

    for (int t = 0; t < 32; t++) {
        if (t + 1 < 32) {
            int s = (t + 1) & 1;
            size_t rofs = (size_t)((t + 1) * 64 + rw) * DHEAD + cofs;
            #pragma unroll
            for (int a = 0; a < 4; a++) {
                const __nv_bfloat16* p = srcs[a] + rofs;
                uint32_t d = smb + (uint32_t)(((s * 4 + a) * AARR + rw * AST + cofs) * 2);
                cpa16(d, p); cpa16(d + 16, p + 8);
            }
            cp_commit();
            cp_wait<1>();
        } else {
            cp_wait<0>();
        }
        __syncthreads();

        const int bf = t & 1;
        const __nv_bfloat16* Kh_s = sa_mem + (bf * 4 + 0) * AARR;
        const __nv_bfloat16* Kl_s = sa_mem + (bf * 4 + 1) * AARR;
        const __nv_bfloat16* Vh_s = sa_mem + (bf * 4 + 2) * AARR;
        const __nv_bfloat16* Vl_s = sa_mem + (bf * 4 + 3) * AARR;

        // S = Q @ K^T
        float sa[8][4] = {};
        #pragma unroll
        for (int kk = 0; kk < 4; kk++) {
            #pragma unroll
            for (int g = 0; g < 4; g++) {
                uint32_t khf[4], klf[4];
                int off = (g * 16 + lrow) * AST + kk * 16 + lcol;
                ldsm4(khf, &Kh_s[off]);
                ldsm4(klf, &Kl_s[off]);
                #pragma unroll
                for (int o = 0; o < 2; o++) {
                    mma16816(sa[2*g+o], qh[kk], khf[o], khf[o+2]);
                    mma16816(sa[2*g+o], qh[kk], klf[o], klf[o+2]);
                    mma16816(sa[2*g+o], ql[kk], khf[o], khf[o+2]);
                }
            }
        }

        // Online softmax
        float mx0 = -1e30f, mx1 = -1e30f;
        #pragma unroll
        for (int jn = 0; jn < 8; jn++) {
            mx0 = fmaxf(mx0, fmaxf(sa[jn][0], sa[jn][1]));
            mx1 = fmaxf(mx1, fmaxf(sa[jn][2], sa[jn][3]));
        }
        mx0 = fmaxf(mx0, __shfl_xor_sync(0xffffffffu, mx0, 1));
        mx0 = fmaxf(mx0, __shfl_xor_sync(0xffffffffu, mx0, 2));
        mx1 = fmaxf(mx1, __shfl_xor_sync(0xffffffffu, mx1, 1));
        mx1 = fmaxf(mx1, __shfl_xor_sync(0xffffffffu, mx1, 2));

        float mn0 = fmaxf(m0, mx0), mn1 = fmaxf(m1, mx1);
        float c0 = fast_exp(m0 - mn0), c1 = fast_exp(m1 - mn1);
        float s0 = 0.0f, s1 = 0.0f;
        #pragma unroll
        for (int jn = 0; jn < 8; jn++) {
            sa[jn][0] = fast_exp(sa[jn][0] - mn0);
            sa[jn][1] = fast_exp(sa[jn][1] - mn0);
            sa[jn][2] = fast_exp(sa[jn][2] - mn1);
            sa[jn][3] = fast_exp(sa[jn][3] - mn1);
            s0 += sa[jn][0] + sa[jn][1];
            s1 += sa[jn][2] + sa[jn][3];
            ctx[jn][0] *= c0; ctx[jn][1] *= c0;
            ctx[jn][2] *= c1; ctx[jn][3] *= c1;
        }
        s0 += __shfl_xor_sync(0xffffffffu, s0, 1);
        s0 += __shfl_xor_sync(0xffffffffu, s0, 2);
        s1 += __shfl_xor_sync(0xffffffffu, s1, 1);
        s1 += __shfl_xor_sync(0xffffffffu, s1, 2);
        l0 = l0 * c0 + s0;  m0 = mn0;
        l1 = l1 * c1 + s1;  m1 = mn1;

        // Pack P fragments (QK acc layout == PV A-frag layout)
        uint32_t ph[4][4], pl[4][4];
        #pragma unroll
        for (int kc = 0; kc < 4; kc++) {
            ph[kc][0] = split2(sa[2*kc][0],   sa[2*kc][1],   pl[kc][0]);
            ph[kc][1] = split2(sa[2*kc][2],   sa[2*kc][3],   pl[kc][1]);
            ph[kc][2] = split2(sa[2*kc+1][0], sa[2*kc+1][1], pl[kc][2]);
            ph[kc][3] = split2(sa[2*kc+1][2], sa[2*kc+1][3], pl[kc][3]);
        }

        // ctx += P @ V   (V natural [kv][dh], ldsm.trans; pairs (r0,r1),(r2,r3))
        #pragma unroll
        for (int kc = 0; kc < 4; kc++) {
            #pragma unroll
            for (int g = 0; g < 4; g++) {
                uint32_t vhf[4], vlf[4];
                int off = (kc * 16 + lrow) * AST + g * 16 + lcol;
                ldsm4t(vhf, &Vh_s[off]);
                ldsm4t(vlf, &Vl_s[off]);
                #pragma unroll
                for (int o = 0; o < 2; o++) {
                    mma16816(ctx[2*g+o], ph[kc], vhf[2*o], vhf[2*o+1]);
                    mma16816(ctx[2*g+o], ph[kc], vlf[2*o], vlf[2*o+1]);
                    mma16816(ctx[2*g+o], pl[kc], vhf[2*o], vhf[2*o+1]);
                }
            }
        }
        __syncthreads();
    }

    // Finalize: divide by row sums, split to bf16 hi/lo ctx (s,b,D) layout
    const int b = n >> 4, h = n & 15;
    const float inv0 = 1.0f / l0, inv1 = 1.0f / l1;
    const int s0r = q0 + wm + (lane >> 2);
    #pragma unroll
    for (int jn = 0; jn < 8; jn++) {
        int dh = jn * 8 + (lane & 3) * 2;
        size_t o0 = ((size_t)s0r * BATCH + b) * DMODEL + h * DHEAD + dh;
        size_t o1 = ((size_t)(s0r + 8) * BATCH + b) * DMODEL + h * DHEAD + dh;
        uint32_t lo;
        uint32_t hi = split2(ctx[jn][0] * inv0, ctx[jn][1] * inv0, lo);
        *(uint32_t*)&g_Ch[o0] = hi; *(uint32_t*)&g_Cl[o0] = lo;
        hi = split2(ctx[jn][2] * inv1, ctx[jn][3] * inv1, lo);
        *(uint32_t*)&g_Ch[o1] = hi; *(uint32_t*)&g_Cl[o1] = lo;
    }
}

// ---------------------------------------------------------------------------
// LayerNorm (in-place): one block per row of 1024
// ---------------------------------------------------------------------------
__device__ __forceinline__ float block_sum256(float v, float* red)
{
    #pragma unroll
    for (int o = 16; o > 0; o >>= 1) v += __shfl_xor_sync(0xffffffffu, v, o);
    if ((threadIdx.x & 31) == 0) red[threadIdx.x >> 5] = v;
    __syncthreads();
    if (threadIdx.x < 32) {
        float x = (threadIdx.x < 8) ? red[threadIdx.x] : 0.0f;
        #pragma unroll
        for (int o = 4; o > 0; o >>= 1) x += __shfl_xor_sync(0xffffffffu, x, o);
        if (threadIdx.x == 0) red[0] = x;
    }
    __syncthreads();
    float rv = red[0];
    __syncthreads();
    return rv;
}

__global__ void __launch_bounds__(256) ln_kernel(
    float* __restrict__ y, const float* __restrict__ w, const float* __restrict__ bb)
{
    __shared__ float red[8];
    const int rix = blockIdx.x;
    float* row = y + (size_t)rix * DMODEL;
    const int tid = threadIdx.x;

    float v[4];
    #pragma unroll
    for (int p = 0; p < 4; p++) v[p] = row[tid + p * 256];

    float s = v[0] + v[1] + v[2] + v[3];
    float mean = block_sum256(s, red) * (1.0f / DMODEL);

    float ss = 0.0f;
    #pragma unroll
    for (int p = 0; p < 4; p++) { float d = v[p] - mean; ss = fmaf(d, d, ss); }
    float var = block_sum256(ss, red) * (1.0f / DMODEL);
    float rstd = rsqrtf(var + 1e-12f);

    #pragma unroll
    for (int p = 0; p < 4; p++) {
        int c = tid + p * 256;
        row[c] = w[c] * (v[p] - mean) * rstd + bb[c];
    }
}

// ---------------------------------------------------------------------------
extern "C" void kernel_launch(void* const* d_in, const int* in_sizes, int n_in,
                              void* d_out, int out_size)
{
    const float* q_in = (const float*)d_in[0];
    const float* k_in = (const float*)d_in[1];
    const float* v_in = (const float*)d_in[2];
    const float* Wq   = (const float*)d_in[3];
    const float* bq   = (const float*)d_in[4];
    const float* Wk   = (const float*)d_in[5];
    const float* bk   = (const float*)d_in[6];
    const float* Wv   = (const float*)d_in[7];
    const float* bv   = (const float*)d_in[8];
    const float* Wo   = (const float*)d_in[9];
    const float* bo   = (const float*)d_in[10];
    const float* ln_w = (const float*)d_in[11];
    const float* ln_b = (const float*)d_in[12];
    float* out = (float*)d_out;

    static int attr_done = 0;
    if (!attr_done) {
        cudaFuncSetAttribute(gemm_mma, cudaFuncAttributeMaxDynamicSharedMemorySize, GEMM_SMEM);
        cudaFuncSetAttribute(attn_mma, cudaFuncAttributeMaxDynamicSharedMemorySize, ATTN_SMEM);
        attr_done = 1;
    }

    dim3 gg(DMODEL / 128, MROWS / 128);   // (8, 32)

    split_all<<<dim3(1024, 16), 256>>>(q_in, k_in, v_in, Wq, Wk, Wv, Wo);

    gemm_mma<<<gg, 256, GEMM_SMEM>>>(bq, nullptr, nullptr, 0);
    gemm_mma<<<gg, 256, GEMM_SMEM>>>(bk, nullptr, nullptr, 1);
    gemm_mma<<<gg, 256, GEMM_SMEM>>>(bv, nullptr, nullptr, 2);

    attn_mma<<<dim3(S_LEN / 128, BHEADS), 256, ATTN_SMEM>>>();

    gemm_mma<<<gg, 256, GEMM_SMEM>>>(bo, q_in, out, 3);

    ln_kernel<<<MROWS, 256>>>(out, ln_w, ln_b);
}